// round 5
// baseline (speedup 1.0000x reference)
#include <cuda_runtime.h>
#include <math.h>

#define BATCH 1576
#define TT    30
#define DD    1024
#define HH    128
#define MM    (BATCH*TT)   /* 47280 */
#define EPS   1e-5f
#define QSCALE 0.08838834764831845f  /* sqrt(1/128) */

/* ------------------------------------------------------------------ */
/* scratch (device globals: no allocations allowed)                    */
/* ------------------------------------------------------------------ */
__device__ float g_hraw[MM*HH];
__device__ float g_hln [MM*HH];
__device__ float g_h2  [MM*HH];
__device__ float g_g0  [MM];
__device__ float g_gate[MM];
__device__ float g_Wp  [3*HH*HH];   /* n_g-folded Wq,Wk,Wv */
__device__ float g_cvec[3*HH];      /* col sums of n_g*W   */
__device__ float g_dvec[3*HH];      /* n_b@W + bias        */

/* ------------------------------------------------------------------ */
/* tf32 helpers                                                        */
/* ------------------------------------------------------------------ */
__device__ __forceinline__ unsigned f2tf(float x){
    unsigned r; asm("cvt.rna.tf32.f32 %0, %1;" : "=r"(r) : "f"(x)); return r;
}
__device__ __forceinline__ void mma_tf32(float* d, const unsigned* a, const unsigned* b){
    asm volatile("mma.sync.aligned.m16n8k8.row.col.f32.tf32.tf32.f32 "
        "{%0,%1,%2,%3},{%4,%5,%6,%7},{%8,%9},{%0,%1,%2,%3};"
        : "+f"(d[0]), "+f"(d[1]), "+f"(d[2]), "+f"(d[3])
        : "r"(a[0]),"r"(a[1]),"r"(a[2]),"r"(a[3]), "r"(b[0]),"r"(b[1]));
}

/* ------------------------------------------------------------------ */
/* K1/K5: C[M,N] = A[M,K] @ B[K,N] + bias.  BM=BN=128, BK=32, 8 warps */
/* ------------------------------------------------------------------ */
__global__ __launch_bounds__(256,1)
void gemm_bias_kernel(const float* __restrict__ A, const float* __restrict__ Bw,
                      const float* __restrict__ bias, float* __restrict__ C,
                      int M, int N, int K)
{
    __shared__ float As[32*129];   /* [k][m], stride 129: STS conflict-free */
    __shared__ float Bs[32*132];   /* [k][n], stride 132: float4-aligned    */

    const int tid  = threadIdx.x;
    const int wid  = tid >> 5, lane = tid & 31;
    const int m0   = blockIdx.x * 128, n0 = blockIdx.y * 128;
    const int warp_m = (wid & 1) * 64;
    const int warp_n = (wid >> 1) * 32;

    float acc[4][4][4];
    #pragma unroll
    for (int i=0;i<4;i++)
      #pragma unroll
      for (int j=0;j<4;j++)
        #pragma unroll
        for (int l=0;l<4;l++) acc[i][j][l]=0.f;

    const int arow = tid >> 3;        /* 0..31 (+32 steps)  */
    const int ac   = (tid & 7) * 4;   /* k offset (float4)  */
    const int brow = tid >> 5;        /* 0..7 (+8 steps)    */
    const int bc   = lane * 4;        /* n offset (float4)  */

    for (int k0 = 0; k0 < K; k0 += 32){
        #pragma unroll
        for (int i=0;i<4;i++){
            int r  = arow + i*32;
            int gr = m0 + r;
            float4 v = (gr < M) ? *(const float4*)(A + (size_t)gr*K + k0 + ac)
                                : make_float4(0.f,0.f,0.f,0.f);
            As[(ac+0)*129 + r] = v.x;
            As[(ac+1)*129 + r] = v.y;
            As[(ac+2)*129 + r] = v.z;
            As[(ac+3)*129 + r] = v.w;
        }
        #pragma unroll
        for (int i=0;i<4;i++){
            int r = brow + i*8;
            float4 v = *(const float4*)(Bw + (size_t)(k0+r)*N + n0 + bc);
            *(float4*)(&Bs[r*132 + bc]) = v;
        }
        __syncthreads();

        #pragma unroll
        for (int ks=0; ks<4; ks++){
            int kk = ks*8;
            int kq = kk + (lane & 3);
            unsigned af[4][4], bf[4][2];
            #pragma unroll
            for (int mi=0; mi<4; mi++){
                int mrow = warp_m + mi*16 + (lane >> 2);
                af[mi][0] = f2tf(As[ kq     *129 + mrow    ]);
                af[mi][1] = f2tf(As[ kq     *129 + mrow + 8]);
                af[mi][2] = f2tf(As[(kq+4)  *129 + mrow    ]);
                af[mi][3] = f2tf(As[(kq+4)  *129 + mrow + 8]);
            }
            #pragma unroll
            for (int ni=0; ni<4; ni++){
                int ncol = warp_n + ni*8 + (lane >> 2);
                bf[ni][0] = f2tf(Bs[ kq   *132 + ncol]);
                bf[ni][1] = f2tf(Bs[(kq+4)*132 + ncol]);
            }
            #pragma unroll
            for (int mi=0; mi<4; mi++)
                #pragma unroll
                for (int ni=0; ni<4; ni++)
                    mma_tf32(acc[mi][ni], af[mi], bf[ni]);
        }
        __syncthreads();
    }

    #pragma unroll
    for (int mi=0; mi<4; mi++){
        #pragma unroll
        for (int ni=0; ni<4; ni++){
            int col = n0 + warp_n + ni*8 + (lane & 3)*2;
            float b0 = bias[col], b1 = bias[col+1];
            int r0 = m0 + warp_m + mi*16 + (lane >> 2);
            int r1 = r0 + 8;
            if (r0 < M){
                float2 o = make_float2(acc[mi][ni][0]+b0, acc[mi][ni][1]+b1);
                *(float2*)(C + (size_t)r0*N + col) = o;
            }
            if (r1 < M){
                float2 o = make_float2(acc[mi][ni][2]+b0, acc[mi][ni][3]+b1);
                *(float2*)(C + (size_t)r1*N + col) = o;
            }
        }
    }
}

/* ------------------------------------------------------------------ */
/* K2: hln = LN(hraw)*g+b ; g0[row] = mean(hln). 128 thr = 1 row      */
/* ------------------------------------------------------------------ */
__global__ void ln_rowmean_kernel(const float* __restrict__ hraw,
    const float* __restrict__ gg, const float* __restrict__ bb,
    float* __restrict__ hln, float* __restrict__ g0)
{
    int row = blockIdx.x;
    int t   = threadIdx.x;
    float v = hraw[(size_t)row*HH + t];
    float s = v, s2 = v*v;
    #pragma unroll
    for (int o=16;o;o>>=1){
        s  += __shfl_xor_sync(0xffffffffu, s,  o);
        s2 += __shfl_xor_sync(0xffffffffu, s2, o);
    }
    __shared__ float sh[4], sh2[4];
    if ((t&31)==0){ sh[t>>5]=s; sh2[t>>5]=s2; }
    __syncthreads();
    s  = sh[0]+sh[1]+sh[2]+sh[3];
    s2 = sh2[0]+sh2[1]+sh2[2]+sh2[3];
    float mu  = s*(1.0f/HH);
    float var = s2*(1.0f/HH) - mu*mu;
    float rs  = rsqrtf(var + EPS);
    float ov  = (v-mu)*rs*gg[t] + bb[t];
    hln[(size_t)row*HH + t] = ov;
    float so = ov;
    #pragma unroll
    for (int o=16;o;o>>=1) so += __shfl_xor_sync(0xffffffffu, so, o);
    __syncthreads();
    if ((t&31)==0) sh[t>>5]=so;
    __syncthreads();
    if (t==0) g0[row] = (sh[0]+sh[1]+sh[2]+sh[3])*(1.0f/HH);
}

/* ------------------------------------------------------------------ */
/* K3: gate[b,:] = softmax(g0[b,:] @ T_W + T_b)                        */
/* ------------------------------------------------------------------ */
__global__ void gate_kernel(const float* __restrict__ g0,
    const float* __restrict__ TW, const float* __restrict__ Tb,
    float* __restrict__ gate)
{
    int b = blockIdx.x, t = threadIdx.x;
    __shared__ float gs[TT];
    if (t < TT) gs[t] = g0[b*TT + t];
    __syncwarp();
    float y = -1e30f;
    if (t < TT){
        y = Tb[t];
        #pragma unroll 6
        for (int s=0;s<TT;s++) y += gs[s]*TW[s*TT + t];
    }
    float m = y;
    #pragma unroll
    for (int o=16;o;o>>=1) m = fmaxf(m, __shfl_xor_sync(0xffffffffu, m, o));
    float e = (t < TT) ? expf(y - m) : 0.f;
    float sum = e;
    #pragma unroll
    for (int o=16;o;o>>=1) sum += __shfl_xor_sync(0xffffffffu, sum, o);
    if (t < TT) gate[b*TT + t] = e / sum;
}

/* ------------------------------------------------------------------ */
/* K0: fold n_g into Wq/Wk/Wv; c[n]=sum n_g*W; d[n]=n_b@W + bias      */
/* ------------------------------------------------------------------ */
__global__ void prep_kernel(const float* __restrict__ Wq, const float* __restrict__ bq,
                            const float* __restrict__ Wk, const float* __restrict__ bk,
                            const float* __restrict__ Wv, const float* __restrict__ bv,
                            const float* __restrict__ ng, const float* __restrict__ nb)
{
    int which = blockIdx.x;
    const float* W  = (which==0)?Wq:((which==1)?Wk:Wv);
    const float* bs = (which==0)?bq:((which==1)?bk:bv);
    int n = threadIdx.x;
    float c=0.f, d=0.f;
    for (int h=0; h<HH; h++){
        float w  = W[h*HH + n];
        float gw = ng[h]*w;
        g_Wp[which*HH*HH + h*HH + n] = gw;
        c += gw;
        d += nb[h]*w;
    }
    g_cvec[which*HH + n] = c;
    g_dvec[which*HH + n] = d + bs[n];
}

/* ------------------------------------------------------------------ */
/* projection with folded LN: dst = (r*(hg@W') - r*mu*c + d)*qscale   */
/* ------------------------------------------------------------------ */
__device__ __forceinline__ void proj128(const float* __restrict__ hgs,
    const float* __restrict__ W, const float* __restrict__ cv,
    const float* __restrict__ dv, const float* __restrict__ smu,
    const float* __restrict__ srr, float* __restrict__ dst,
    float qscale, int wid, int lane)
{
    const int warp_m = (wid & 3) * 32;
    const int warp_n = (wid >> 2) * 64;
    float acc[2][8][4];
    #pragma unroll
    for (int i=0;i<2;i++)
      #pragma unroll
      for (int j=0;j<8;j++)
        #pragma unroll
        for (int l=0;l<4;l++) acc[i][j][l]=0.f;

    #pragma unroll
    for (int ks=0; ks<16; ks++){
        int kk = ks*8;
        int k0 = kk + (lane & 3);
        unsigned af[2][4];
        #pragma unroll
        for (int mi=0; mi<2; mi++){
            int r = warp_m + mi*16 + (lane >> 2);
            af[mi][0] = f2tf(hgs[ r   *132 + k0    ]);
            af[mi][1] = f2tf(hgs[(r+8)*132 + k0    ]);
            af[mi][2] = f2tf(hgs[ r   *132 + k0 + 4]);
            af[mi][3] = f2tf(hgs[(r+8)*132 + k0 + 4]);
        }
        #pragma unroll
        for (int ni=0; ni<8; ni++){
            int n = warp_n + ni*8 + (lane >> 2);
            unsigned bf[2];
            bf[0] = f2tf(__ldg(&W[ k0   *HH + n]));
            bf[1] = f2tf(__ldg(&W[(k0+4)*HH + n]));
            #pragma unroll
            for (int mi=0; mi<2; mi++) mma_tf32(acc[mi][ni], af[mi], bf);
        }
    }
    #pragma unroll
    for (int mi=0; mi<2; mi++)
    #pragma unroll
    for (int ni=0; ni<8; ni++){
        int r0 = warp_m + mi*16 + (lane >> 2);
        int c0 = warp_n + ni*8 + (lane & 3)*2;
        #pragma unroll
        for (int hh=0; hh<2; hh++){
            int r = r0 + hh*8;
            float rrv = srr[r], muv = smu[r];
            float v0 = (rrv*acc[mi][ni][hh*2]   - rrv*muv*cv[c0]   + dv[c0]  ) * qscale;
            float v1 = (rrv*acc[mi][ni][hh*2+1] - rrv*muv*cv[c0+1] + dv[c0+1]) * qscale;
            dst[r*132 + c0]   = v0;
            dst[r*132 + c0+1] = v1;
        }
    }
}

/* ------------------------------------------------------------------ */
/* K4: fused attention. 1 block = 4 batches padded to 32 rows each.   */
/* ------------------------------------------------------------------ */
__global__ __launch_bounds__(256,1)
void attn_kernel(const float* __restrict__ Wo, const float* __restrict__ bo)
{
    extern __shared__ float sm[];
    float* hg  = sm;                    /* 128*132  gated h (residual)  */
    float* bA  = sm + 128*132;          /* q then v                     */
    float* bB  = sm + 2*128*132;        /* k then o                     */
    float* ssc = sm + 3*128*132;        /* 4 * 32*33 scores/attn        */
    float* smu = ssc + 4*32*33;         /* 128 */
    float* srr = smu + 128;             /* 128 */

    const int tid  = threadIdx.x;
    const int wid  = tid >> 5, lane = tid & 31;
    const int bbase = blockIdx.x * 4;

    /* 1. load gated h */
    for (int idx = tid; idx < 128*128; idx += 256){
        int r = idx >> 7, c = idx & 127;
        int g = r >> 5,  t = r & 31;
        float v = 0.f;
        if (t < TT){
            int grow = (bbase + g)*TT + t;
            v = g_hln[(size_t)grow*HH + c] * g_gate[grow];
        }
        hg[r*132 + c] = v;
    }
    __syncthreads();

    /* 2. LN row stats on hg */
    if (tid < 128){
        float s=0.f, s2=0.f;
        #pragma unroll 8
        for (int c=0;c<128;c++){ float v = hg[tid*132+c]; s+=v; s2+=v*v; }
        float mu  = s*(1.f/128.f);
        float var = s2*(1.f/128.f) - mu*mu;
        smu[tid] = mu;
        srr[tid] = rsqrtf(var + EPS);
    }
    __syncthreads();

    /* 3. q -> bA (scaled), k -> bB */
    proj128(hg, g_Wp,          g_cvec,       g_dvec,       smu, srr, bA, QSCALE, wid, lane);
    proj128(hg, g_Wp + HH*HH,  g_cvec + HH,  g_dvec + HH,  smu, srr, bB, 1.f,    wid, lane);
    __syncthreads();

    /* 4. scores = q @ k^T  (per batch 32x32) */
    {
        int g = wid >> 1, mt = wid & 1;
        float sacc[4][4];
        #pragma unroll
        for (int i=0;i<4;i++)
          #pragma unroll
          for (int j=0;j<4;j++) sacc[i][j]=0.f;

        #pragma unroll
        for (int ks=0; ks<16; ks++){
            int kk = ks*8;
            int k0 = kk + (lane & 3);
            int r  = 32*g + mt*16 + (lane >> 2);
            unsigned af[4];
            af[0] = f2tf(bA[ r   *132 + k0    ]);
            af[1] = f2tf(bA[(r+8)*132 + k0    ]);
            af[2] = f2tf(bA[ r   *132 + k0 + 4]);
            af[3] = f2tf(bA[(r+8)*132 + k0 + 4]);
            #pragma unroll
            for (int nt=0; nt<4; nt++){
                int n = 32*g + nt*8 + (lane >> 2);
                unsigned bf[2];
                bf[0] = f2tf(bB[n*132 + k0    ]);
                bf[1] = f2tf(bB[n*132 + k0 + 4]);
                mma_tf32(sacc[nt], af, bf);
            }
        }
        float* p = ssc + g*1056;
        #pragma unroll
        for (int nt=0; nt<4; nt++){
            int t0 = mt*16 + (lane >> 2);
            int c0 = nt*8 + (lane & 3)*2;
            p[ t0   *33 + c0  ] = (c0   < TT) ? sacc[nt][0] : -1e30f;
            p[ t0   *33 + c0+1] = (c0+1 < TT) ? sacc[nt][1] : -1e30f;
            p[(t0+8)*33 + c0  ] = (c0   < TT) ? sacc[nt][2] : -1e30f;
            p[(t0+8)*33 + c0+1] = (c0+1 < TT) ? sacc[nt][3] : -1e30f;
        }
    }
    __syncthreads();

    /* 5. row softmax over 30 valid cols */
    if (tid < 128){
        int g = tid >> 5, t = tid & 31;
        float* p = ssc + g*1056 + t*33;
        float m = -1e30f;
        #pragma unroll 6
        for (int c=0;c<TT;c++) m = fmaxf(m, p[c]);
        float e[TT]; float sum = 0.f;
        #pragma unroll 6
        for (int c=0;c<TT;c++){ e[c] = expf(p[c]-m); sum += e[c]; }
        float inv = 1.f/sum;
        #pragma unroll 6
        for (int c=0;c<TT;c++) p[c] = e[c]*inv;
        p[30] = 0.f; p[31] = 0.f;
    }
    __syncthreads();

    /* 6. v -> bA (overwrites q) */
    proj128(hg, g_Wp + 2*HH*HH, g_cvec + 2*HH, g_dvec + 2*HH, smu, srr, bA, 1.f, wid, lane);
    __syncthreads();

    /* 7. o = attn @ v -> bB (overwrites k) */
    {
        int g = wid >> 1, mt = wid & 1;
        float oacc[16][4];
        #pragma unroll
        for (int i=0;i<16;i++)
          #pragma unroll
          for (int j=0;j<4;j++) oacc[i][j]=0.f;

        const float* p = ssc + g*1056;
        #pragma unroll
        for (int ks=0; ks<4; ks++){
            int kk = ks*8;
            int k0 = kk + (lane & 3);
            int t0 = mt*16 + (lane >> 2);
            unsigned af[4];
            af[0] = f2tf(p[ t0   *33 + k0    ]);
            af[1] = f2tf(p[(t0+8)*33 + k0    ]);
            af[2] = f2tf(p[ t0   *33 + k0 + 4]);
            af[3] = f2tf(p[(t0+8)*33 + k0 + 4]);
            #pragma unroll
            for (int nt=0; nt<16; nt++){
                int n = nt*8 + (lane >> 2);
                unsigned bf[2];
                bf[0] = f2tf(bA[(32*g + k0    )*132 + n]);
                bf[1] = f2tf(bA[(32*g + k0 + 4)*132 + n]);
                mma_tf32(oacc[nt], af, bf);
            }
        }
        #pragma unroll
        for (int nt=0; nt<16; nt++){
            int t0 = mt*16 + (lane >> 2);
            int c0 = nt*8 + (lane & 3)*2;
            bB[(32*g + t0  )*132 + c0  ] = oacc[nt][0];
            bB[(32*g + t0  )*132 + c0+1] = oacc[nt][1];
            bB[(32*g + t0+8)*132 + c0  ] = oacc[nt][2];
            bB[(32*g + t0+8)*132 + c0+1] = oacc[nt][3];
        }
    }
    __syncthreads();

    /* 8. h2 = o @ Wo + bo + hg  -> global */
    {
        int warp_m = (wid & 3)*32, warp_n = (wid >> 2)*64;
        float acc[2][8][4];
        #pragma unroll
        for (int i=0;i<2;i++)
          #pragma unroll
          for (int j=0;j<8;j++)
            #pragma unroll
            for (int l=0;l<4;l++) acc[i][j][l]=0.f;

        #pragma unroll
        for (int ks=0; ks<16; ks++){
            int kk = ks*8;
            int k0 = kk + (lane & 3);
            unsigned af[2][4];
            #pragma unroll
            for (int mi=0; mi<2; mi++){
                int r = warp_m + mi*16 + (lane >> 2);
                af[mi][0] = f2tf(bB[ r   *132 + k0    ]);
                af[mi][1] = f2tf(bB[(r+8)*132 + k0    ]);
                af[mi][2] = f2tf(bB[ r   *132 + k0 + 4]);
                af[mi][3] = f2tf(bB[(r+8)*132 + k0 + 4]);
            }
            #pragma unroll
            for (int ni=0; ni<8; ni++){
                int n = warp_n + ni*8 + (lane >> 2);
                unsigned bf[2];
                bf[0] = f2tf(__ldg(&Wo[ k0   *HH + n]));
                bf[1] = f2tf(__ldg(&Wo[(k0+4)*HH + n]));
                #pragma unroll
                for (int mi=0; mi<2; mi++) mma_tf32(acc[mi][ni], af[mi], bf);
            }
        }
        #pragma unroll
        for (int mi=0; mi<2; mi++)
        #pragma unroll
        for (int ni=0; ni<8; ni++){
            int r0 = warp_m + mi*16 + (lane >> 2);
            int c0 = warp_n + ni*8 + (lane & 3)*2;
            #pragma unroll
            for (int hh=0; hh<2; hh++){
                int r = r0 + hh*8;
                int g = r >> 5, t = r & 31;
                if (t < TT){
                    size_t orow = (size_t)((bbase + g)*TT + t)*HH;
                    float v0 = acc[mi][ni][hh*2]   + bo[c0]   + hg[r*132 + c0];
                    float v1 = acc[mi][ni][hh*2+1] + bo[c0+1] + hg[r*132 + c0+1];
                    g_h2[orow + c0]   = v0;
                    g_h2[orow + c0+1] = v1;
                }
            }
        }
    }
}

/* ------------------------------------------------------------------ */
extern "C" void kernel_launch(void* const* d_in, const int* in_sizes, int n_in,
                              void* d_out, int out_size)
{
    const float* x    = (const float*)d_in[0];
    const float* W1   = (const float*)d_in[1];
    const float* b1   = (const float*)d_in[2];
    const float* ln_g = (const float*)d_in[3];
    const float* ln_b = (const float*)d_in[4];
    const float* T_W  = (const float*)d_in[5];
    const float* T_b  = (const float*)d_in[6];
    const float* Wq   = (const float*)d_in[7];
    const float* bq   = (const float*)d_in[8];
    const float* Wk   = (const float*)d_in[9];
    const float* bk   = (const float*)d_in[10];
    const float* Wv   = (const float*)d_in[11];
    const float* bv   = (const float*)d_in[12];
    const float* Wo   = (const float*)d_in[13];
    const float* bo   = (const float*)d_in[14];
    const float* n_g  = (const float*)d_in[15];
    const float* n_b  = (const float*)d_in[16];
    const float* W2   = (const float*)d_in[17];
    const float* b2   = (const float*)d_in[18];
    float* out = (float*)d_out;

    float *hraw, *hln, *h2, *g0, *gate;
    cudaGetSymbolAddress((void**)&hraw, g_hraw);
    cudaGetSymbolAddress((void**)&hln,  g_hln);
    cudaGetSymbolAddress((void**)&h2,   g_h2);
    cudaGetSymbolAddress((void**)&g0,   g_g0);
    cudaGetSymbolAddress((void**)&gate, g_gate);

    static const int ATTN_SMEM = (3*128*132 + 4*32*33 + 256) * 4;  /* 220672 B */
    cudaFuncSetAttribute(attn_kernel, cudaFuncAttributeMaxDynamicSharedMemorySize, ATTN_SMEM);

    /* K1: h_raw = x @ W1 + b1 */
    gemm_bias_kernel<<<dim3((MM+127)/128, 1), 256>>>(x, W1, b1, hraw, MM, HH, DD);
    /* K2: hln = LN(hraw); g0 = rowmean(hln) */
    ln_rowmean_kernel<<<MM, 128>>>(hraw, ln_g, ln_b, hln, g0);
    /* K3: gate = softmax(g0 @ T_W + T_b) */
    gate_kernel<<<BATCH, 32>>>(g0, T_W, T_b, gate);
    /* K0: fold n_g/n_b into projection weights */
    prep_kernel<<<3, 128>>>(Wq, bq, Wk, bk, Wv, bv, n_g, n_b);
    /* K4: fused gated attention -> h2 */
    attn_kernel<<<BATCH/4, 256, ATTN_SMEM>>>(Wo, bo);
    /* K5: out = h2 @ W2 + b2 */
    gemm_bias_kernel<<<dim3((MM+127)/128, 8), 256>>>(h2, W2, b2, out, MM, DD, HH);
}

// round 6
// speedup vs baseline: 1.6352x; 1.6352x over previous
#include <cuda_runtime.h>
#include <math.h>
#include <stdint.h>

#define BATCH 1576
#define TT    30
#define DD    1024
#define HH    128
#define MM    (BATCH*TT)   /* 47280 */
#define EPS   1e-5f
#define QSCALE 0.08838834764831845f  /* sqrt(1/128) */
#define GG    2            /* batches per attn block */

/* ------------------------------------------------------------------ */
/* scratch (device globals: no allocations allowed)                    */
/* ------------------------------------------------------------------ */
__device__ float g_hln [MM*HH];
__device__ float g_h2  [MM*HH];
__device__ float g_g0  [MM];
__device__ float g_gate[MM];
__device__ float g_Wp  [3*HH*HH];   /* n_g-folded Wq,Wk,Wv */
__device__ float g_cvec[3*HH];
__device__ float g_dvec[3*HH];
__device__ float g_cpart[3*8*HH];
__device__ float g_dpart[3*8*HH];

/* ------------------------------------------------------------------ */
/* tf32 + cp.async helpers                                             */
/* ------------------------------------------------------------------ */
__device__ __forceinline__ unsigned f2tf(float x){
    unsigned r; asm("cvt.rna.tf32.f32 %0, %1;" : "=r"(r) : "f"(x)); return r;
}
__device__ __forceinline__ void mma_tf32(float* d, const unsigned* a, const unsigned* b){
    asm volatile("mma.sync.aligned.m16n8k8.row.col.f32.tf32.tf32.f32 "
        "{%0,%1,%2,%3},{%4,%5,%6,%7},{%8,%9},{%0,%1,%2,%3};"
        : "+f"(d[0]), "+f"(d[1]), "+f"(d[2]), "+f"(d[3])
        : "r"(a[0]),"r"(a[1]),"r"(a[2]),"r"(a[3]), "r"(b[0]),"r"(b[1]));
}
__device__ __forceinline__ uint32_t s2u(const void* p){
    return (uint32_t)__cvta_generic_to_shared(p);
}
#define CPA(dst,src,nbytes) asm volatile("cp.async.ca.shared.global [%0], [%1], 16, %2;" :: "r"(dst), "l"(src), "r"(nbytes))
#define CPC()  asm volatile("cp.async.commit_group;" ::: "memory")
#define CPW1() asm volatile("cp.async.wait_group 1;" ::: "memory")
#define CPW0() asm volatile("cp.async.wait_group 0;" ::: "memory")

/* smem layout for GEMMs (floats):
   As[s]: 128x36 at s*4608 ; Bs[s]: 32x132 at 9216 + s*4224 ; total 17664 */
#define GEMM_SMEM_FLOATS 17664

__device__ __forceinline__ void gemm_prefetch(const float* __restrict__ A,
    const float* __restrict__ Bw, int m0, int n0, int k0,
    int M, int K, int N, int tid, float* sm, int s)
{
    uint32_t asb = s2u(sm + s*4608);
    uint32_t bsb = s2u(sm + 9216 + s*4224);
    #pragma unroll
    for (int j=0;j<4;j++){
        int lin = j*256 + tid;
        int r = lin>>3, kc = (lin&7)*4;
        int gr = m0 + r;
        const float* src = A + (size_t)(gr < M ? gr : 0)*K + k0 + kc;
        CPA(asb + (uint32_t)(r*36+kc)*4u, src, (gr<M)?16:0);
    }
    #pragma unroll
    for (int j=0;j<4;j++){
        int lin = j*256 + tid;
        int r = lin>>5, nc = (lin&31)*4;
        const float* src = Bw + (size_t)(k0+r)*N + n0 + nc;
        CPA(bsb + (uint32_t)(r*132+nc)*4u, src, 16);
    }
    CPC();
}

__device__ __forceinline__ void gemm_compute(const float* __restrict__ As,
    const float* __restrict__ Bs, float acc[4][4][4], int warp_m, int warp_n, int lane)
{
    #pragma unroll
    for (int ks=0; ks<4; ks++){
        int kq = ks*8 + (lane&3);
        unsigned af[4][4], bf[4][2];
        #pragma unroll
        for (int mi=0; mi<4; mi++){
            int mrow = warp_m + mi*16 + (lane>>2);
            af[mi][0]=f2tf(As[mrow*36+kq]);
            af[mi][1]=f2tf(As[(mrow+8)*36+kq]);
            af[mi][2]=f2tf(As[mrow*36+kq+4]);
            af[mi][3]=f2tf(As[(mrow+8)*36+kq+4]);
        }
        #pragma unroll
        for (int ni=0; ni<4; ni++){
            int nc = warp_n + ni*8 + (lane>>2);
            bf[ni][0]=f2tf(Bs[kq*132+nc]);
            bf[ni][1]=f2tf(Bs[(kq+4)*132+nc]);
        }
        #pragma unroll
        for (int mi=0;mi<4;mi++)
            #pragma unroll
            for (int ni=0;ni<4;ni++)
                mma_tf32(acc[mi][ni], af[mi], bf[ni]);
    }
}

/* ------------------------------------------------------------------ */
/* K1 fused: h = x@W1 + b1 ; hln = LN(h)*g+b -> g_hln ; g0 = rowmean   */
/* ------------------------------------------------------------------ */
__global__ __launch_bounds__(256,1)
void gemm1_ln_kernel(const float* __restrict__ x, const float* __restrict__ W1,
                     const float* __restrict__ bias,
                     const float* __restrict__ gg, const float* __restrict__ bb)
{
    extern __shared__ float sm[];
    const int tid=threadIdx.x, wid=tid>>5, lane=tid&31;
    const int m0 = blockIdx.x*128;
    const int warp_m=(wid&1)*64, warp_n=(wid>>1)*32;

    float acc[4][4][4] = {};

    gemm_prefetch(x, W1, m0, 0, 0, MM, DD, HH, tid, sm, 0);
    for (int it=0; it<32; it++){
        int s = it&1;
        if (it+1<32){ gemm_prefetch(x, W1, m0, 0, (it+1)*32, MM, DD, HH, tid, sm, s^1); CPW1(); }
        else        { CPW0(); }
        __syncthreads();
        gemm_compute(sm + s*4608, sm + 9216 + s*4224, acc, warp_m, warp_n, lane);
        __syncthreads();
    }

    /* epilogue: Cs = acc + bias (smem, stride 132), then per-row LN */
    float* Cs = sm;   /* alias: As/Bs dead after final sync */
    #pragma unroll
    for (int mi=0;mi<4;mi++){
        #pragma unroll
        for (int ni=0;ni<4;ni++){
            int col = warp_n + ni*8 + (lane&3)*2;
            float b0=bias[col], b1v=bias[col+1];
            int r0 = warp_m + mi*16 + (lane>>2), r1=r0+8;
            Cs[r0*132+col]   = acc[mi][ni][0]+b0;
            Cs[r0*132+col+1] = acc[mi][ni][1]+b1v;
            Cs[r1*132+col]   = acc[mi][ni][2]+b0;
            Cs[r1*132+col+1] = acc[mi][ni][3]+b1v;
        }
    }
    __syncthreads();

    for (int rr=0; rr<16; rr++){
        int row = wid*16 + rr;
        int grow = m0 + row;
        if (grow >= MM) break;
        float v0=Cs[row*132+lane],    v1=Cs[row*132+lane+32];
        float v2=Cs[row*132+lane+64], v3=Cs[row*132+lane+96];
        float s_ = v0+v1+v2+v3;
        float s2 = v0*v0+v1*v1+v2*v2+v3*v3;
        #pragma unroll
        for (int o=16;o;o>>=1){
            s_ += __shfl_xor_sync(0xffffffffu, s_, o);
            s2 += __shfl_xor_sync(0xffffffffu, s2, o);
        }
        float mu = s_*(1.f/128.f);
        float var = s2*(1.f/128.f) - mu*mu;
        float rs = rsqrtf(var + EPS);
        size_t base = (size_t)grow*HH;
        float o0 = (v0-mu)*rs*gg[lane]    + bb[lane];
        float o1 = (v1-mu)*rs*gg[lane+32] + bb[lane+32];
        float o2 = (v2-mu)*rs*gg[lane+64] + bb[lane+64];
        float o3 = (v3-mu)*rs*gg[lane+96] + bb[lane+96];
        g_hln[base+lane]    = o0;
        g_hln[base+lane+32] = o1;
        g_hln[base+lane+64] = o2;
        g_hln[base+lane+96] = o3;
        float so = o0+o1+o2+o3;
        #pragma unroll
        for (int o=16;o;o>>=1) so += __shfl_xor_sync(0xffffffffu, so, o);
        if (lane==0) g_g0[grow] = so*(1.f/128.f);
    }
}

/* ------------------------------------------------------------------ */
/* K5: C = A @ B + bias (double-buffered)                              */
/* ------------------------------------------------------------------ */
__global__ __launch_bounds__(256,1)
void gemm_bias_db(const float* __restrict__ A, const float* __restrict__ Bw,
                  const float* __restrict__ bias, float* __restrict__ C,
                  int M, int N, int K)
{
    extern __shared__ float sm[];
    const int tid=threadIdx.x, wid=tid>>5, lane=tid&31;
    const int m0 = blockIdx.x*128, n0 = blockIdx.y*128;
    const int warp_m=(wid&1)*64, warp_n=(wid>>1)*32;
    const int nIt = K>>5;

    float acc[4][4][4] = {};

    gemm_prefetch(A, Bw, m0, n0, 0, M, K, N, tid, sm, 0);
    for (int it=0; it<nIt; it++){
        int s = it&1;
        if (it+1<nIt){ gemm_prefetch(A, Bw, m0, n0, (it+1)*32, M, K, N, tid, sm, s^1); CPW1(); }
        else         { CPW0(); }
        __syncthreads();
        gemm_compute(sm + s*4608, sm + 9216 + s*4224, acc, warp_m, warp_n, lane);
        __syncthreads();
    }

    #pragma unroll
    for (int mi=0;mi<4;mi++){
        #pragma unroll
        for (int ni=0;ni<4;ni++){
            int col = n0 + warp_n + ni*8 + (lane&3)*2;
            float b0 = bias[col], b1v = bias[col+1];
            int r0 = m0 + warp_m + mi*16 + (lane>>2);
            int r1 = r0 + 8;
            if (r0 < M){
                float2 o = make_float2(acc[mi][ni][0]+b0, acc[mi][ni][1]+b1v);
                *(float2*)(C + (size_t)r0*N + col) = o;
            }
            if (r1 < M){
                float2 o = make_float2(acc[mi][ni][2]+b0, acc[mi][ni][3]+b1v);
                *(float2*)(C + (size_t)r1*N + col) = o;
            }
        }
    }
}

/* ------------------------------------------------------------------ */
/* gate: gate[b,:] = softmax(g0[b,:] @ T_W + T_b)                      */
/* ------------------------------------------------------------------ */
__global__ void gate_kernel(const float* __restrict__ g0,
    const float* __restrict__ TW, const float* __restrict__ Tb,
    float* __restrict__ gate)
{
    int b = blockIdx.x, t = threadIdx.x;
    __shared__ float gs[TT];
    if (t < TT) gs[t] = g0[b*TT + t];
    __syncwarp();
    float y = -1e30f;
    if (t < TT){
        y = Tb[t];
        #pragma unroll 6
        for (int s=0;s<TT;s++) y += gs[s]*TW[s*TT + t];
    }
    float m = y;
    #pragma unroll
    for (int o=16;o;o>>=1) m = fmaxf(m, __shfl_xor_sync(0xffffffffu, m, o));
    float e = (t < TT) ? expf(y - m) : 0.f;
    float sum = e;
    #pragma unroll
    for (int o=16;o;o>>=1) sum += __shfl_xor_sync(0xffffffffu, sum, o);
    if (t < TT) gate[b*TT + t] = e / sum;
}

/* ------------------------------------------------------------------ */
/* prep: fold n_g into Wq/Wk/Wv (parallel over h-chunks) + reduce      */
/* ------------------------------------------------------------------ */
__global__ void prep_kernel(const float* __restrict__ Wq, const float* __restrict__ Wk,
                            const float* __restrict__ Wv,
                            const float* __restrict__ ng, const float* __restrict__ nb)
{
    int which = blockIdx.x, hb = blockIdx.y*16, n = threadIdx.x;
    const float* W = (which==0)?Wq:((which==1)?Wk:Wv);
    float c=0.f, d=0.f;
    #pragma unroll
    for (int i=0;i<16;i++){
        int h = hb + i;
        float w  = W[h*HH + n];
        float gw = ng[h]*w;
        g_Wp[which*HH*HH + h*HH + n] = gw;
        c += gw;
        d += nb[h]*w;
    }
    g_cpart[(which*8 + blockIdx.y)*HH + n] = c;
    g_dpart[(which*8 + blockIdx.y)*HH + n] = d;
}

__global__ void prep_reduce(const float* __restrict__ bq, const float* __restrict__ bk,
                            const float* __restrict__ bv)
{
    int which = blockIdx.x, n = threadIdx.x;
    float c=0.f, d=0.f;
    #pragma unroll
    for (int y=0;y<8;y++){
        c += g_cpart[(which*8+y)*HH + n];
        d += g_dpart[(which*8+y)*HH + n];
    }
    const float* b = (which==0)?bq:((which==1)?bk:bv);
    g_cvec[which*HH + n] = c;
    g_dvec[which*HH + n] = d + b[n];
}

/* ------------------------------------------------------------------ */
/* projection with folded LN: dst = (r*(hg@W') - r*mu*c + d)*qscale    */
/* output 64x128, 8 warps, warp tile 32x32                             */
/* ------------------------------------------------------------------ */
__device__ __forceinline__ void proj64(const float* __restrict__ hgs,
    const float* __restrict__ W, const float* __restrict__ cv,
    const float* __restrict__ dv, const float* __restrict__ smu,
    const float* __restrict__ srr, float* __restrict__ dst,
    float qscale, int wid, int lane)
{
    const int warp_m = (wid & 1) * 32;
    const int warp_n = (wid >> 1) * 32;
    float acc[2][4][4] = {};

    #pragma unroll
    for (int ks=0; ks<16; ks++){
        int k0 = ks*8 + (lane & 3);
        unsigned af[2][4];
        #pragma unroll
        for (int mi=0; mi<2; mi++){
            int r = warp_m + mi*16 + (lane >> 2);
            af[mi][0] = f2tf(hgs[ r   *132 + k0    ]);
            af[mi][1] = f2tf(hgs[(r+8)*132 + k0    ]);
            af[mi][2] = f2tf(hgs[ r   *132 + k0 + 4]);
            af[mi][3] = f2tf(hgs[(r+8)*132 + k0 + 4]);
        }
        #pragma unroll
        for (int ni=0; ni<4; ni++){
            int n = warp_n + ni*8 + (lane >> 2);
            unsigned bf[2];
            bf[0] = f2tf(__ldg(&W[ k0   *HH + n]));
            bf[1] = f2tf(__ldg(&W[(k0+4)*HH + n]));
            #pragma unroll
            for (int mi=0; mi<2; mi++) mma_tf32(acc[mi][ni], af[mi], bf);
        }
    }
    #pragma unroll
    for (int mi=0; mi<2; mi++)
    #pragma unroll
    for (int ni=0; ni<4; ni++){
        int r0 = warp_m + mi*16 + (lane >> 2);
        int c0 = warp_n + ni*8 + (lane & 3)*2;
        #pragma unroll
        for (int hh=0; hh<2; hh++){
            int r = r0 + hh*8;
            float rrv = srr[r], muv = smu[r];
            dst[r*132 + c0]   = (rrv*acc[mi][ni][hh*2]   - rrv*muv*cv[c0]   + dv[c0]  ) * qscale;
            dst[r*132 + c0+1] = (rrv*acc[mi][ni][hh*2+1] - rrv*muv*cv[c0+1] + dv[c0+1]) * qscale;
        }
    }
}

/* ------------------------------------------------------------------ */
/* attn: 1 block = 2 batches (64 padded rows). smem 110336 B.          */
/* ------------------------------------------------------------------ */
__global__ __launch_bounds__(256,1)
void attn_kernel(const float* __restrict__ Wo, const float* __restrict__ bo)
{
    extern __shared__ float sm[];
    float* hg  = sm;            /* 64*132 gated h (residual + proj in) */
    float* bA  = sm + 8448;     /* q then v                            */
    float* bB  = sm + 16896;    /* k then o                            */
    float* ssc = sm + 25344;    /* 2 * 32*33 scores/attn               */
    float* smu = sm + 27456;    /* 64 */
    float* srr = sm + 27520;    /* 64 */

    const int tid  = threadIdx.x;
    const int wid  = tid >> 5, lane = tid & 31;
    const int bbase = blockIdx.x * GG;

    /* 1. load gated h */
    for (int idx = tid; idx < 64*128; idx += 256){
        int r = idx >> 7, c = idx & 127;
        int g = r >> 5,  t = r & 31;
        float v = 0.f;
        if (t < TT){
            int grow = (bbase + g)*TT + t;
            v = g_hln[(size_t)grow*HH + c] * g_gate[grow];
        }
        hg[r*132 + c] = v;
    }
    __syncthreads();

    /* 2. LN row stats */
    if (tid < 64){
        float s=0.f, s2=0.f;
        #pragma unroll 8
        for (int c=0;c<128;c++){ float v = hg[tid*132+c]; s+=v; s2+=v*v; }
        float mu  = s*(1.f/128.f);
        float var = s2*(1.f/128.f) - mu*mu;
        smu[tid] = mu;
        srr[tid] = rsqrtf(var + EPS);
    }
    __syncthreads();

    /* 3. q -> bA (scaled), k -> bB */
    proj64(hg, g_Wp,         g_cvec,      g_dvec,      smu, srr, bA, QSCALE, wid, lane);
    proj64(hg, g_Wp + HH*HH, g_cvec + HH, g_dvec + HH, smu, srr, bB, 1.f,    wid, lane);
    __syncthreads();

    /* 4. scores = q @ k^T (per batch 32x32; 4 warps per batch) */
    {
        int g = wid >> 2, mt = wid & 1, nh = (wid >> 1) & 1;
        float sacc[2][4] = {};
        #pragma unroll
        for (int ks=0; ks<16; ks++){
            int k0 = ks*8 + (lane & 3);
            int r  = g*32 + mt*16 + (lane >> 2);
            unsigned af[4];
            af[0] = f2tf(bA[ r   *132 + k0    ]);
            af[1] = f2tf(bA[(r+8)*132 + k0    ]);
            af[2] = f2tf(bA[ r   *132 + k0 + 4]);
            af[3] = f2tf(bA[(r+8)*132 + k0 + 4]);
            #pragma unroll
            for (int nt=0; nt<2; nt++){
                int n = g*32 + nh*16 + nt*8 + (lane >> 2);
                unsigned bf[2];
                bf[0] = f2tf(bB[n*132 + k0    ]);
                bf[1] = f2tf(bB[n*132 + k0 + 4]);
                mma_tf32(sacc[nt], af, bf);
            }
        }
        float* p = ssc + g*1056;
        #pragma unroll
        for (int nt=0; nt<2; nt++){
            int t0 = mt*16 + (lane >> 2);
            int c0 = nh*16 + nt*8 + (lane & 3)*2;
            p[ t0   *33 + c0  ] = (c0   < TT) ? sacc[nt][0] : -1e30f;
            p[ t0   *33 + c0+1] = (c0+1 < TT) ? sacc[nt][1] : -1e30f;
            p[(t0+8)*33 + c0  ] = (c0   < TT) ? sacc[nt][2] : -1e30f;
            p[(t0+8)*33 + c0+1] = (c0+1 < TT) ? sacc[nt][3] : -1e30f;
        }
    }
    __syncthreads();

    /* 5. row softmax over 30 valid cols */
    if (tid < 64){
        int g = tid >> 5, t = tid & 31;
        float* p = ssc + g*1056 + t*33;
        float m = -1e30f;
        #pragma unroll 6
        for (int c=0;c<TT;c++) m = fmaxf(m, p[c]);
        float e[TT]; float sum = 0.f;
        #pragma unroll 6
        for (int c=0;c<TT;c++){ e[c] = expf(p[c]-m); sum += e[c]; }
        float inv = 1.f/sum;
        #pragma unroll 6
        for (int c=0;c<TT;c++) p[c] = e[c]*inv;
        p[30] = 0.f; p[31] = 0.f;
    }
    __syncthreads();

    /* 6. v -> bA (overwrites q) */
    proj64(hg, g_Wp + 2*HH*HH, g_cvec + 2*HH, g_dvec + 2*HH, smu, srr, bA, 1.f, wid, lane);
    __syncthreads();

    /* 7. o = attn @ v -> bB (overwrites k). 4 warps/batch: 16 rows x 64 cols */
    {
        int g = wid >> 2, mt = wid & 1, nh = (wid >> 1) & 1;
        float oacc[8][4] = {};
        const float* p = ssc + g*1056;
        #pragma unroll
        for (int ks=0; ks<4; ks++){
            int k0 = ks*8 + (lane & 3);
            int t0 = mt*16 + (lane >> 2);
            unsigned af[4];
            af[0] = f2tf(p[ t0   *33 + k0    ]);
            af[1] = f2tf(p[(t0+8)*33 + k0    ]);
            af[2] = f2tf(p[ t0   *33 + k0 + 4]);
            af[3] = f2tf(p[(t0+8)*33 + k0 + 4]);
            #pragma unroll
            for (int nt=0; nt<8; nt++){
                int n = nh*64 + nt*8 + (lane >> 2);
                unsigned bf[2];
                bf[0] = f2tf(bA[(g*32 + k0    )*132 + n]);
                bf[1] = f2tf(bA[(g*32 + k0 + 4)*132 + n]);
                mma_tf32(oacc[nt], af, bf);
            }
        }
        #pragma unroll
        for (int nt=0; nt<8; nt++){
            int t0 = mt*16 + (lane >> 2);
            int c0 = nh*64 + nt*8 + (lane & 3)*2;
            bB[(g*32 + t0  )*132 + c0  ] = oacc[nt][0];
            bB[(g*32 + t0  )*132 + c0+1] = oacc[nt][1];
            bB[(g*32 + t0+8)*132 + c0  ] = oacc[nt][2];
            bB[(g*32 + t0+8)*132 + c0+1] = oacc[nt][3];
        }
    }
    __syncthreads();

    /* 8. h2 = o @ Wo + bo + hg -> global */
    {
        const int warp_m = (wid & 1)*32, warp_n = (wid >> 1)*32;
        float acc[2][4][4] = {};
        #pragma unroll
        for (int ks=0; ks<16; ks++){
            int k0 = ks*8 + (lane & 3);
            unsigned af[2][4];
            #pragma unroll
            for (int mi=0; mi<2; mi++){
                int r = warp_m + mi*16 + (lane >> 2);
                af[mi][0] = f2tf(bB[ r   *132 + k0    ]);
                af[mi][1] = f2tf(bB[(r+8)*132 + k0    ]);
                af[mi][2] = f2tf(bB[ r   *132 + k0 + 4]);
                af[mi][3] = f2tf(bB[(r+8)*132 + k0 + 4]);
            }
            #pragma unroll
            for (int ni=0; ni<4; ni++){
                int n = warp_n + ni*8 + (lane >> 2);
                unsigned bf[2];
                bf[0] = f2tf(__ldg(&Wo[ k0   *HH + n]));
                bf[1] = f2tf(__ldg(&Wo[(k0+4)*HH + n]));
                #pragma unroll
                for (int mi=0; mi<2; mi++) mma_tf32(acc[mi][ni], af[mi], bf);
            }
        }
        #pragma unroll
        for (int mi=0; mi<2; mi++)
        #pragma unroll
        for (int ni=0; ni<4; ni++){
            int r0 = warp_m + mi*16 + (lane >> 2);
            int c0 = warp_n + ni*8 + (lane & 3)*2;
            #pragma unroll
            for (int hh=0; hh<2; hh++){
                int r = r0 + hh*8;
                int g = r >> 5, t = r & 31;
                if (t < TT){
                    size_t orow = (size_t)((bbase + g)*TT + t)*HH;
                    g_h2[orow + c0]   = acc[mi][ni][hh*2]   + bo[c0]   + hg[r*132 + c0];
                    g_h2[orow + c0+1] = acc[mi][ni][hh*2+1] + bo[c0+1] + hg[r*132 + c0+1];
                }
            }
        }
    }
}

/* ------------------------------------------------------------------ */
extern "C" void kernel_launch(void* const* d_in, const int* in_sizes, int n_in,
                              void* d_out, int out_size)
{
    const float* x    = (const float*)d_in[0];
    const float* W1   = (const float*)d_in[1];
    const float* b1   = (const float*)d_in[2];
    const float* ln_g = (const float*)d_in[3];
    const float* ln_b = (const float*)d_in[4];
    const float* T_W  = (const float*)d_in[5];
    const float* T_b  = (const float*)d_in[6];
    const float* Wq   = (const float*)d_in[7];
    const float* bq   = (const float*)d_in[8];
    const float* Wk   = (const float*)d_in[9];
    const float* bk   = (const float*)d_in[10];
    const float* Wv   = (const float*)d_in[11];
    const float* bv   = (const float*)d_in[12];
    const float* Wo   = (const float*)d_in[13];
    const float* bo   = (const float*)d_in[14];
    const float* n_g  = (const float*)d_in[15];
    const float* n_b  = (const float*)d_in[16];
    const float* W2   = (const float*)d_in[17];
    const float* b2   = (const float*)d_in[18];
    float* out = (float*)d_out;

    float *h2, *g0, *gate;
    cudaGetSymbolAddress((void**)&h2,   g_h2);
    cudaGetSymbolAddress((void**)&g0,   g_g0);
    cudaGetSymbolAddress((void**)&gate, g_gate);

    const int GEMM_SMEM = GEMM_SMEM_FLOATS * 4;        /* 70656 B  */
    const int ATTN_SMEM = 27584 * 4;                   /* 110336 B */
    cudaFuncSetAttribute(gemm1_ln_kernel, cudaFuncAttributeMaxDynamicSharedMemorySize, GEMM_SMEM);
    cudaFuncSetAttribute(gemm_bias_db,    cudaFuncAttributeMaxDynamicSharedMemorySize, GEMM_SMEM);
    cudaFuncSetAttribute(attn_kernel,     cudaFuncAttributeMaxDynamicSharedMemorySize, ATTN_SMEM);

    /* fold n_g/n_b into projection weights (parallel + deterministic reduce) */
    prep_kernel<<<dim3(3,8), 128>>>(Wq, Wk, Wv, n_g, n_b);
    prep_reduce<<<3, 128>>>(bq, bk, bv);
    /* fused: hln = LN(x@W1+b1); g0 = rowmean(hln) */
    gemm1_ln_kernel<<<(MM+127)/128, 256, GEMM_SMEM>>>(x, W1, b1, ln_g, ln_b);
    /* gate = softmax(g0 @ T_W + T_b) */
    gate_kernel<<<BATCH, 32>>>(g0, T_W, T_b, gate);
    /* fused gated attention -> h2 */
    attn_kernel<<<BATCH/GG, 256, ATTN_SMEM>>>(Wo, bo);
    /* out = h2 @ W2 + b2 */
    gemm_bias_db<<<dim3((MM+127)/128, 8), 256, GEMM_SMEM>>>(h2, W2, b2, out, MM, DD, HH);
}